// round 10
// baseline (speedup 1.0000x reference)
#include <cuda_runtime.h>
#include <cuda_bf16.h>
#include <cstdint>
#include <cmath>

// ===========================================================================
// MultiheadChannelAttention — Round 6: HMMA bf16x3 + fused C/head-mean GEMM.
// All GEMMs NT: C[M,N] = alpha * A[M,K] @ B[N,K]^T, operands bf16 (hi,lo);
// C = Ahi*Bhi + Ahi*Blo + Alo*Bhi, fp32 accum. K may be segmented (per-head
// pointer blocks) so the attention-context GEMM folds the head mean.
// ===========================================================================

// ------------------------- sizes (elements) --------------------------------
constexpr long long N_EMB1 = 8LL*1024*64;
constexpr long long N_EMB2 = 8LL*1024*128;
constexpr long long N_EMB3 = 8LL*1024*256;
constexpr long long N_EMB4 = 8LL*1024*512;
constexpr long long N_EMBA = 8LL*1024*960;
constexpr long long N_WQ1 = 4LL*64*64;
constexpr long long N_WQ2 = 4LL*128*128;
constexpr long long N_WQ3 = 4LL*256*256;
constexpr long long N_WQ4 = 4LL*512*512;
constexpr long long N_WK  = 4LL*960*960;
constexpr long long N_WV  = 4LL*960*960;
constexpr long long N_WO1 = 64LL*64;
constexpr long long N_WO2 = 128LL*128;
constexpr long long N_WO3 = 256LL*256;
constexpr long long N_WO4 = 512LL*512;
constexpr long long N_KT  = 32LL*960*1024;
constexpr long long N_VV  = 32LL*1024*960;
constexpr long long N_Q   = 32LL*512*1024;
constexpr long long N_A   = 32LL*512*960;
constexpr long long N_CM  = 8LL*1024*512;

// ------------------------- device scratch (hi at [0..n), lo at [n..2n)) ----
__device__ __align__(128) __nv_bfloat16 g_emb1p[2*N_EMB1];
__device__ __align__(128) __nv_bfloat16 g_emb2p[2*N_EMB2];
__device__ __align__(128) __nv_bfloat16 g_emb3p[2*N_EMB3];
__device__ __align__(128) __nv_bfloat16 g_emb4p[2*N_EMB4];
__device__ __align__(128) __nv_bfloat16 g_embap[2*N_EMBA];
__device__ __align__(128) __nv_bfloat16 g_wq1p[2*N_WQ1];
__device__ __align__(128) __nv_bfloat16 g_wq2p[2*N_WQ2];
__device__ __align__(128) __nv_bfloat16 g_wq3p[2*N_WQ3];
__device__ __align__(128) __nv_bfloat16 g_wq4p[2*N_WQ4];
__device__ __align__(128) __nv_bfloat16 g_wkp [2*N_WK];
__device__ __align__(128) __nv_bfloat16 g_wvp [2*N_WV];
__device__ __align__(128) __nv_bfloat16 g_wo1p[2*N_WO1];
__device__ __align__(128) __nv_bfloat16 g_wo2p[2*N_WO2];
__device__ __align__(128) __nv_bfloat16 g_wo3p[2*N_WO3];
__device__ __align__(128) __nv_bfloat16 g_wo4p[2*N_WO4];
__device__ __align__(128) __nv_bfloat16 g_ktp [2*N_KT];
__device__ __align__(128) __nv_bfloat16 g_vp  [2*N_VV];
__device__ __align__(128) __nv_bfloat16 g_qp  [2*N_Q];
__device__ __align__(128) __nv_bfloat16 g_ap  [2*N_A];
__device__ __align__(128) __nv_bfloat16 g_cmp [2*N_CM];
__device__ float g_S[N_A];      // fp32 scores (per-branch reuse)
__device__ float g_invstd[32];

// ------------------------- helpers -----------------------------------------
__device__ __forceinline__ uint32_t smem_u32(const void* p){
    uint32_t a;
    asm("{ .reg .u64 t; cvta.to.shared.u64 t, %1; cvt.u32.u64 %0, t; }"
        : "=r"(a) : "l"(p));
    return a;
}
__device__ __forceinline__ void ldsm_x4(uint32_t a, uint32_t& r0, uint32_t& r1,
                                        uint32_t& r2, uint32_t& r3){
    asm volatile("ldmatrix.sync.aligned.m8n8.x4.shared.b16 {%0,%1,%2,%3}, [%4];"
                 : "=r"(r0), "=r"(r1), "=r"(r2), "=r"(r3) : "r"(a));
}
__device__ __forceinline__ void mma_bf16(float* c, const uint32_t* a,
                                         uint32_t b0, uint32_t b1){
    asm volatile(
        "mma.sync.aligned.m16n8k16.row.col.f32.bf16.bf16.f32 "
        "{%0,%1,%2,%3}, {%4,%5,%6,%7}, {%8,%9}, {%0,%1,%2,%3};"
        : "+f"(c[0]), "+f"(c[1]), "+f"(c[2]), "+f"(c[3])
        : "r"(a[0]), "r"(a[1]), "r"(a[2]), "r"(a[3]), "r"(b0), "r"(b1));
}

// ------------------------- tile geometry -----------------------------------
constexpr int BM = 128, BN = 128;
constexpr int ROWB = 80;                           // 64B data + 16B pad per row
constexpr int MAT = 128 * ROWB;                    // 10240 B per matrix tile
constexpr int OFF_AH = 0;
constexpr int OFF_AL = MAT;
constexpr int OFF_BH = 2 * MAT;
constexpr int OFF_BL = 3 * MAT;
constexpr int STAGE_BYTES = 4 * MAT;               // 40960 B
constexpr int DYN_SMEM = 2 * STAGE_BYTES;          // 81920 B
constexpr int NTHREADS = 128;

// ===========================================================================
// bf16x3 batched NT GEMM via mma.sync. z-mode: 0 shared, 1 z/H, 2 z%H, 3 z.
// K runs over segments of segK elements; segment s of operand X starts at
// Xbase + s*xSegStride, rows have stride segK. (segK == K -> plain GEMM.)
// 4 warps arranged 2(m) x 2(n); warp tile 64x64.
// ===========================================================================
__global__ __launch_bounds__(NTHREADS, 2)
void gemm_bf16x3(
    const __nv_bfloat16* __restrict__ Ahi, const __nv_bfloat16* __restrict__ Alo,
    const __nv_bfloat16* __restrict__ Bhi, const __nv_bfloat16* __restrict__ Blo,
    float* __restrict__ Cf, __nv_bfloat16* __restrict__ Chi, __nv_bfloat16* __restrict__ Clo,
    int M, int N, int K, int segK,
    long long aStride, long long bStride,
    long long aSegStride, long long bSegStride,
    int modeA, int modeB, int H, float alpha)
{
    extern __shared__ char dynsmem[];
    const uint32_t sb = smem_u32(dynsmem);

    const int tid  = threadIdx.x;
    const int wid  = tid >> 5;
    const int lane = tid & 31;
    const int wm   = wid >> 1;            // 0..1 -> m offset 64*wm
    const int wn   = wid & 1;             // 0..1 -> n offset 64*wn

    const int z  = blockIdx.z;
    const int zA = (modeA == 0) ? 0 : (modeA == 1) ? (z / H) : (modeA == 2) ? (z % H) : z;
    const int zB = (modeB == 0) ? 0 : (modeB == 1) ? (z / H) : (modeB == 2) ? (z % H) : z;
    const __nv_bfloat16* pA[2] = { Ahi + (long long)zA * aStride, Alo + (long long)zA * aStride };
    const __nv_bfloat16* pB[2] = { Bhi + (long long)zB * bStride, Blo + (long long)zB * bStride };

    const int m0 = blockIdx.y * BM;
    const int n0 = blockIdx.x * BN;
    const int NC = K >> 5;                // chunks of 32

    // ------- async stage fill: 2048 x 16B segments, 16 per thread ----------
    auto load_stage = [&](int stage, int kc) {
        const int k0   = kc << 5;
        const int segi = k0 / segK;             // which K-segment (h)
        const int kin  = k0 - segi * segK;      // offset within segment
        const uint32_t stb = sb + (uint32_t)(stage * STAGE_BYTES);
#pragma unroll
        for (int it = 0; it < 16; ++it) {
            const int idx = it * NTHREADS + tid;     // 0..2047
            const int mat = idx >> 9;                // 0..3: AH, AL, BH, BL
            const int rem = idx & 511;
            const int row = rem >> 2;                // 0..127
            const int sg  = rem & 3;                 // 16B segment in row
            int g, lim; const __nv_bfloat16* src; long long segoff;
            if (mat < 2) { g = m0 + row; lim = M; src = pA[mat]; segoff = (long long)segi * aSegStride; }
            else         { g = n0 + row; lim = N; src = pB[mat - 2]; segoff = (long long)segi * bSegStride; }
            const int valid = (g < lim);
            const uint32_t dst = stb + (uint32_t)(mat * MAT) + (uint32_t)(row * ROWB + sg * 16);
            const char* sp = (const char*)(src + segoff + (long long)(valid ? g : 0) * segK + kin + sg * 8);
            const uint32_t sz = valid ? 16u : 0u;
            asm volatile("cp.async.cg.shared.global [%0], [%1], 16, %2;"
                         :: "r"(dst), "l"(sp), "r"(sz));
        }
        asm volatile("cp.async.commit_group;" ::: "memory");
    };

    float acc[4][8][4];
#pragma unroll
    for (int t = 0; t < 4; t++)
#pragma unroll
        for (int n = 0; n < 8; n++)
#pragma unroll
            for (int j = 0; j < 4; j++) acc[t][n][j] = 0.f;

    load_stage(0, 0);
    if (NC > 1) load_stage(1, 1);

    const uint32_t lrow = (uint32_t)(lane & 15) * ROWB;
    const uint32_t lseg = (uint32_t)(lane >> 4) * 16;

    for (int kc = 0; kc < NC; ++kc) {
        if (kc + 2 <= NC) { asm volatile("cp.async.wait_group 1;" ::: "memory"); }
        else              { asm volatile("cp.async.wait_group 0;" ::: "memory"); }
        __syncthreads();

        const int st = kc & 1;
        const uint32_t stb = sb + (uint32_t)(st * STAGE_BYTES);
        const uint32_t aHb = stb + OFF_AH, aLb = stb + OFF_AL;
        const uint32_t bHb = stb + OFF_BH, bLb = stb + OFF_BL;

#pragma unroll
        for (int kk = 0; kk < 2; ++kk) {
            const uint32_t koff = (uint32_t)kk * 32 + lseg;
            uint32_t aH[4][4], aL[4][4], bH[4][4], bL[4][4];
#pragma unroll
            for (int t = 0; t < 4; ++t) {
                const uint32_t ro = (uint32_t)(wm * 64 + t * 16) * ROWB + lrow + koff;
                ldsm_x4(aHb + ro, aH[t][0], aH[t][1], aH[t][2], aH[t][3]);
                ldsm_x4(aLb + ro, aL[t][0], aL[t][1], aL[t][2], aL[t][3]);
            }
#pragma unroll
            for (int p = 0; p < 4; ++p) {
                const uint32_t ro = (uint32_t)(wn * 64 + p * 16) * ROWB + lrow + koff;
                ldsm_x4(bHb + ro, bH[p][0], bH[p][1], bH[p][2], bH[p][3]);
                ldsm_x4(bLb + ro, bL[p][0], bL[p][1], bL[p][2], bL[p][3]);
            }
#pragma unroll
            for (int p = 0; p < 4; ++p) {
#pragma unroll
                for (int t = 0; t < 4; ++t) {
                    mma_bf16(acc[t][2*p],   aH[t], bH[p][0], bH[p][2]);
                    mma_bf16(acc[t][2*p],   aH[t], bL[p][0], bL[p][2]);
                    mma_bf16(acc[t][2*p],   aL[t], bH[p][0], bH[p][2]);
                    mma_bf16(acc[t][2*p+1], aH[t], bH[p][1], bH[p][3]);
                    mma_bf16(acc[t][2*p+1], aH[t], bL[p][1], bL[p][3]);
                    mma_bf16(acc[t][2*p+1], aL[t], bH[p][1], bH[p][3]);
                }
            }
        }
        __syncthreads();
        if (kc + 2 < NC) load_stage(st, kc + 2);
    }

    // ------- epilogue ------------------------------------------------------
    const int grp  = lane >> 2;
    const int tid4 = lane & 3;
#pragma unroll
    for (int t = 0; t < 4; ++t) {
#pragma unroll
        for (int n = 0; n < 8; ++n) {
            const int gn = n0 + wn * 64 + n * 8 + tid4 * 2;
            if (gn >= N) continue;
#pragma unroll
            for (int half = 0; half < 2; ++half) {
                const int gm = m0 + wm * 64 + t * 16 + grp + half * 8;
                if (gm >= M) continue;
                const float v0 = alpha * acc[t][n][half * 2 + 0];
                const float v1 = alpha * acc[t][n][half * 2 + 1];
                const long long base = (long long)z * M * N + (long long)gm * N + gn;
                if (Cf) {
                    *reinterpret_cast<float2*>(Cf + base) = make_float2(v0, v1);
                } else {
                    __nv_bfloat162 hp = __floats2bfloat162_rn(v0, v1);
                    __nv_bfloat162 lp = __floats2bfloat162_rn(v0 - __bfloat162float(hp.x),
                                                              v1 - __bfloat162float(hp.y));
                    *reinterpret_cast<__nv_bfloat162*>(Chi + base) = hp;
                    *reinterpret_cast<__nv_bfloat162*>(Clo + base) = lp;
                }
            }
        }
    }
}

// ===========================================================================
// split fp32 -> bf16 (hi, lo)
// ===========================================================================
__global__ __launch_bounds__(256) void split_kernel(
    const float* __restrict__ src, __nv_bfloat16* __restrict__ hi,
    __nv_bfloat16* __restrict__ lo, long long n)
{
    long long i = (long long)blockIdx.x * blockDim.x + threadIdx.x;
    const long long stride = (long long)gridDim.x * blockDim.x;
    for (; i < n; i += stride) {
        const float x = src[i];
        const __nv_bfloat16 h = __float2bfloat16(x);
        hi[i] = h;
        lo[i] = __float2bfloat16(x - __bfloat162float(h));
    }
}

// ===========================================================================
// per-(b,h) biased variance over d x KV -> inv_std (mean cancels in softmax)
// ===========================================================================
__global__ __launch_bounds__(256) void stats_kernel(
    const float* __restrict__ S, float* __restrict__ invstd, int elems)
{
    const int bh = blockIdx.x;
    const float4* p = reinterpret_cast<const float4*>(S + (long long)bh * elems);
    const int n4 = elems >> 2;
    float s = 0.f, s2 = 0.f;
    for (int i = threadIdx.x; i < n4; i += 256) {
        float4 v = p[i];
        s  += v.x + v.y + v.z + v.w;
        s2 += v.x * v.x + v.y * v.y + v.z * v.z + v.w * v.w;
    }
    __shared__ float sh0[256], sh1[256];
    sh0[threadIdx.x] = s; sh1[threadIdx.x] = s2;
    __syncthreads();
    for (int off = 128; off > 0; off >>= 1) {
        if (threadIdx.x < off) {
            sh0[threadIdx.x] += sh0[threadIdx.x + off];
            sh1[threadIdx.x] += sh1[threadIdx.x + off];
        }
        __syncthreads();
    }
    if (threadIdx.x == 0) {
        const float inv = 1.f / (float)elems;
        const float m   = sh0[0] * inv;
        const float var = sh1[0] * inv - m * m;
        invstd[bh] = rsqrtf(var + 1e-5f);
    }
}

// ===========================================================================
// row softmax over KV with inv_std scaling; writes bf16 (hi, lo) pair
// ===========================================================================
__global__ __launch_bounds__(256) void softmax_kernel(
    const float* __restrict__ S, const float* __restrict__ invstd,
    __nv_bfloat16* __restrict__ Ahi, __nv_bfloat16* __restrict__ Alo,
    int d, int KV)
{
    const long long row = blockIdx.x;           // bh*d + e
    const int bh = (int)(row / d);
    const float is = invstd[bh];
    const float* p = S + row * KV;
    const long long ob = row * KV;
    const int tid = threadIdx.x;

    float vals[4];
    int cnt = 0;
    float mx = -1e30f;
    for (int i = tid; i < KV; i += 256) {
        const float v = p[i] * is;
        vals[cnt++] = v;
        mx = fmaxf(mx, v);
    }
    __shared__ float sh[256];
    sh[tid] = mx; __syncthreads();
    for (int off = 128; off > 0; off >>= 1) {
        if (tid < off) sh[tid] = fmaxf(sh[tid], sh[tid + off]);
        __syncthreads();
    }
    mx = sh[0];
    __syncthreads();

    float s = 0.f;
    for (int c = 0; c < cnt; c++) { vals[c] = __expf(vals[c] - mx); s += vals[c]; }
    sh[tid] = s; __syncthreads();
    for (int off = 128; off > 0; off >>= 1) {
        if (tid < off) sh[tid] += sh[tid + off];
        __syncthreads();
    }
    const float rs = 1.f / sh[0];
    cnt = 0;
    for (int i = tid; i < KV; i += 256) {
        const float a = vals[cnt++] * rs;
        const __nv_bfloat16 h = __float2bfloat16(a);
        Ahi[ob + i] = h;
        Alo[ob + i] = __float2bfloat16(a - __bfloat162float(h));
    }
}

// ===========================================================================
extern "C" void kernel_launch(void* const* d_in, const int* in_sizes, int n_in,
                              void* d_out, int out_size)
{
    (void)in_sizes; (void)n_in; (void)out_size;
    const float* emb[4]  = {(const float*)d_in[0], (const float*)d_in[1],
                            (const float*)d_in[2], (const float*)d_in[3]};
    const float* emb_all = (const float*)d_in[4];
    const float* WQ[4]   = {(const float*)d_in[5], (const float*)d_in[6],
                            (const float*)d_in[7], (const float*)d_in[8]};
    const float* WK      = (const float*)d_in[9];
    const float* WV      = (const float*)d_in[10];
    const float* WO[4]   = {(const float*)d_in[11], (const float*)d_in[12],
                            (const float*)d_in[13], (const float*)d_in[14]};
    float* out = (float*)d_out;

    __nv_bfloat16 *embp[4], *embap, *wqp[4], *wkp, *wvp, *wop[4];
    __nv_bfloat16 *ktp, *vp, *qp, *ap, *cmp;
    float *S, *invstd;
    cudaGetSymbolAddress((void**)&embp[0], g_emb1p);
    cudaGetSymbolAddress((void**)&embp[1], g_emb2p);
    cudaGetSymbolAddress((void**)&embp[2], g_emb3p);
    cudaGetSymbolAddress((void**)&embp[3], g_emb4p);
    cudaGetSymbolAddress((void**)&embap,   g_embap);
    cudaGetSymbolAddress((void**)&wqp[0],  g_wq1p);
    cudaGetSymbolAddress((void**)&wqp[1],  g_wq2p);
    cudaGetSymbolAddress((void**)&wqp[2],  g_wq3p);
    cudaGetSymbolAddress((void**)&wqp[3],  g_wq4p);
    cudaGetSymbolAddress((void**)&wkp,     g_wkp);
    cudaGetSymbolAddress((void**)&wvp,     g_wvp);
    cudaGetSymbolAddress((void**)&wop[0],  g_wo1p);
    cudaGetSymbolAddress((void**)&wop[1],  g_wo2p);
    cudaGetSymbolAddress((void**)&wop[2],  g_wo3p);
    cudaGetSymbolAddress((void**)&wop[3],  g_wo4p);
    cudaGetSymbolAddress((void**)&ktp,     g_ktp);
    cudaGetSymbolAddress((void**)&vp,      g_vp);
    cudaGetSymbolAddress((void**)&qp,      g_qp);
    cudaGetSymbolAddress((void**)&ap,      g_ap);
    cudaGetSymbolAddress((void**)&cmp,     g_cmp);
    cudaGetSymbolAddress((void**)&S,       g_S);
    cudaGetSymbolAddress((void**)&invstd,  g_invstd);

    cudaFuncSetAttribute(gemm_bf16x3, cudaFuncAttributeMaxDynamicSharedMemorySize, DYN_SMEM);

    const int Bsz = 8, H = 4, Nn = 1024, KV = 960;
    const int df[4] = {64, 128, 256, 512};
    const float scale = 1.0f / sqrtf((float)KV);

    auto split = [](const float* s, __nv_bfloat16* p, long long n) {
        int blocks = (int)(((n + 255) / 256 < 4096) ? (n + 255) / 256 : 4096);
        split_kernel<<<blocks, 256>>>(s, p, p + n, n);
    };
    const long long nEmb[4] = {N_EMB1, N_EMB2, N_EMB3, N_EMB4};
    const long long nWQ[4]  = {N_WQ1, N_WQ2, N_WQ3, N_WQ4};
    const long long nWO[4]  = {N_WO1, N_WO2, N_WO3, N_WO4};

    // full generality gemm wrapper
    auto gemmSeg = [&](const __nv_bfloat16* Ah, long long an,
                       const __nv_bfloat16* Bh, long long bn,
                       float* Cf, __nv_bfloat16* Ch, long long cn,
                       int M, int N, int K, int segK,
                       long long aS, long long bS, long long aSS, long long bSS,
                       int mA, int mB, int Hh, int Z, float al) {
        dim3 g((unsigned)((N + BN - 1) / BN), (unsigned)((M + BM - 1) / BM), (unsigned)Z);
        gemm_bf16x3<<<g, NTHREADS, DYN_SMEM>>>(Ah, Ah + an, Bh, Bh + bn,
                                               Cf, Ch, Ch ? Ch + cn : nullptr,
                                               M, N, K, segK, aS, bS, aSS, bSS,
                                               mA, mB, Hh, al);
    };
    auto gemm = [&](const __nv_bfloat16* Ah, long long an,
                    const __nv_bfloat16* Bh, long long bn,
                    float* Cf, __nv_bfloat16* Ch, long long cn,
                    int M, int N, int K, long long aS, long long bS,
                    int mA, int mB, int Hh, int Z, float al) {
        gemmSeg(Ah, an, Bh, bn, Cf, Ch, cn, M, N, K, K, aS, bS, 0LL, 0LL,
                mA, mB, Hh, Z, al);
    };

    // --- launch-order: 5 splits, then KT GEMM as launch index 5 (ncu -s 5) --
    split(emb_all, embap, N_EMBA);          // 0
    split(WK, wkp, N_WK);                   // 1
    split(WV, wvp, N_WV);                   // 2
    split(emb[3], embp[3], nEmb[3]);        // 3
    split(WQ[3], wqp[3], nWQ[3]);           // 4

    // 5: KT[bh][j][n]: A=WK (per h), B=emb_all (per b)   <-- profiled launch
    gemm(wkp, N_WK, embap, N_EMBA, nullptr, ktp, N_KT,
         KV, Nn, KV, 960LL*960, 1024LL*960, 2, 1, H, Bsz*H, 1.f);
    // V[bh][n][j]: A=emb_all (per b), B=WV (per h)
    gemm(embap, N_EMBA, wvp, N_WV, nullptr, vp, N_VV,
         Nn, KV, KV, 1024LL*960, 960LL*960, 1, 2, H, Bsz*H, 1.f);

    for (int i = 0; i < 3; i++) split(emb[i], embp[i], nEmb[i]);
    for (int i = 0; i < 3; i++) split(WQ[i], wqp[i], nWQ[i]);
    for (int i = 0; i < 4; i++) split(WO[i], wop[i], nWO[i]);

    long long out_off = 0;
    for (int br = 0; br < 4; br++) {
        const int d = df[br];

        // Q[bh][e][n]: A=WQ (per h), B=emb (per b)
        gemm(wqp[br], nWQ[br], embp[br], nEmb[br], nullptr, qp, N_Q,
             d, Nn, d, (long long)d*d, 1024LL*d, 2, 1, H, Bsz*H, 1.f);

        // S[bh][e][j] = scale * Q @ KT^T  (fp32 out)
        gemm(qp, N_Q, ktp, N_KT, S, nullptr, 0,
             d, KV, Nn, (long long)d*1024, 960LL*1024, 3, 3, H, Bsz*H, scale);

        stats_kernel<<<Bsz*H, 256>>>(S, invstd, d * KV);
        softmax_kernel<<<Bsz*H*d, 256>>>(S, invstd, ap, ap + N_A, d, KV);

        // Fused context + head-mean + transpose:
        // Cm[b][n][e] = 0.25 * sum_{h,j} V[b,h][n][j] * A[b,h][e][j]
        // NT GEMM: M=1024 (n over V rows), N=d (e over A rows), K=4*960 seg 960.
        gemmSeg(vp, N_VV, ap, N_A, nullptr, cmp, N_CM,
                Nn, d, 4 * KV, KV,
                (long long)H * Nn * KV,          // V per-b stride
                (long long)H * d * KV,           // A per-b stride
                (long long)Nn * KV,              // V per-h segment stride
                (long long)d * KV,               // A per-h segment stride
                3, 3, 1, Bsz, 0.25f);

        // O[b][n][f]: A=Cm (per b), B=WO (shared) -> fp32 to d_out
        gemm(cmp, N_CM, wop[br], nWO[br], out + out_off, nullptr, 0,
             Nn, d, d, 1024LL*d, 0LL, 3, 0, 1, Bsz, 1.f);

        out_off += (long long)Bsz * Nn * d;
    }
}

// round 11
// speedup vs baseline: 1.1255x; 1.1255x over previous
#include <cuda_runtime.h>
#include <cuda_bf16.h>
#include <cstdint>
#include <cmath>

// ===========================================================================
// MultiheadChannelAttention — Round 7: HMMA bf16x3, acc-RAW-free MMA bursts,
// merged split kernel, GEMM-first launch order for profiling.
// All GEMMs NT: C[M,N] = alpha * A[M,K] @ B[N,K]^T, operands bf16 (hi,lo);
// C = Ahi*Bhi + Ahi*Blo + Alo*Bhi, fp32 accum.
// ===========================================================================

// ------------------------- sizes (elements) --------------------------------
constexpr long long N_EMB1 = 8LL*1024*64;
constexpr long long N_EMB2 = 8LL*1024*128;
constexpr long long N_EMB3 = 8LL*1024*256;
constexpr long long N_EMB4 = 8LL*1024*512;
constexpr long long N_EMBA = 8LL*1024*960;
constexpr long long N_WQ1 = 4LL*64*64;
constexpr long long N_WQ2 = 4LL*128*128;
constexpr long long N_WQ3 = 4LL*256*256;
constexpr long long N_WQ4 = 4LL*512*512;
constexpr long long N_WK  = 4LL*960*960;
constexpr long long N_WV  = 4LL*960*960;
constexpr long long N_WO1 = 64LL*64;
constexpr long long N_WO2 = 128LL*128;
constexpr long long N_WO3 = 256LL*256;
constexpr long long N_WO4 = 512LL*512;
constexpr long long N_KT  = 32LL*960*1024;
constexpr long long N_VV  = 32LL*1024*960;
constexpr long long N_Q1  = 32LL*64*1024;
constexpr long long N_Q2  = 32LL*128*1024;
constexpr long long N_Q3  = 32LL*256*1024;
constexpr long long N_Q4  = 32LL*512*1024;
constexpr long long N_A   = 32LL*512*960;
constexpr long long N_CC  = 32LL*512*1024;
constexpr long long N_CM  = 8LL*1024*512;

// ------------------------- device scratch (hi at [0..n), lo at [n..2n)) ----
__device__ __align__(128) __nv_bfloat16 g_emb1p[2*N_EMB1];
__device__ __align__(128) __nv_bfloat16 g_emb2p[2*N_EMB2];
__device__ __align__(128) __nv_bfloat16 g_emb3p[2*N_EMB3];
__device__ __align__(128) __nv_bfloat16 g_emb4p[2*N_EMB4];
__device__ __align__(128) __nv_bfloat16 g_embap[2*N_EMBA];
__device__ __align__(128) __nv_bfloat16 g_wq1p[2*N_WQ1];
__device__ __align__(128) __nv_bfloat16 g_wq2p[2*N_WQ2];
__device__ __align__(128) __nv_bfloat16 g_wq3p[2*N_WQ3];
__device__ __align__(128) __nv_bfloat16 g_wq4p[2*N_WQ4];
__device__ __align__(128) __nv_bfloat16 g_wkp [2*N_WK];
__device__ __align__(128) __nv_bfloat16 g_wvp [2*N_WV];
__device__ __align__(128) __nv_bfloat16 g_wo1p[2*N_WO1];
__device__ __align__(128) __nv_bfloat16 g_wo2p[2*N_WO2];
__device__ __align__(128) __nv_bfloat16 g_wo3p[2*N_WO3];
__device__ __align__(128) __nv_bfloat16 g_wo4p[2*N_WO4];
__device__ __align__(128) __nv_bfloat16 g_ktp [2*N_KT];
__device__ __align__(128) __nv_bfloat16 g_vp  [2*N_VV];
__device__ __align__(128) __nv_bfloat16 g_q1p [2*N_Q1];
__device__ __align__(128) __nv_bfloat16 g_q2p [2*N_Q2];
__device__ __align__(128) __nv_bfloat16 g_q3p [2*N_Q3];
__device__ __align__(128) __nv_bfloat16 g_q4p [2*N_Q4];
__device__ __align__(128) __nv_bfloat16 g_ap  [2*N_A];
__device__ __align__(128) __nv_bfloat16 g_cmp [2*N_CM];
__device__ float g_S[N_A];      // fp32 scores (per-branch reuse)
__device__ float g_C[N_CC];     // fp32 context (per-branch reuse)
__device__ float g_invstd[32];

// ------------------------- helpers -----------------------------------------
__device__ __forceinline__ uint32_t smem_u32(const void* p){
    uint32_t a;
    asm("{ .reg .u64 t; cvta.to.shared.u64 t, %1; cvt.u32.u64 %0, t; }"
        : "=r"(a) : "l"(p));
    return a;
}
__device__ __forceinline__ void ldsm_x4(uint32_t a, uint32_t& r0, uint32_t& r1,
                                        uint32_t& r2, uint32_t& r3){
    asm volatile("ldmatrix.sync.aligned.m8n8.x4.shared.b16 {%0,%1,%2,%3}, [%4];"
                 : "=r"(r0), "=r"(r1), "=r"(r2), "=r"(r3) : "r"(a));
}
__device__ __forceinline__ void mma_bf16(float* c, const uint32_t* a,
                                         uint32_t b0, uint32_t b1){
    asm volatile(
        "mma.sync.aligned.m16n8k16.row.col.f32.bf16.bf16.f32 "
        "{%0,%1,%2,%3}, {%4,%5,%6,%7}, {%8,%9}, {%0,%1,%2,%3};"
        : "+f"(c[0]), "+f"(c[1]), "+f"(c[2]), "+f"(c[3])
        : "r"(a[0]), "r"(a[1]), "r"(a[2]), "r"(a[3]), "r"(b0), "r"(b1));
}

// ------------------------- tile geometry -----------------------------------
constexpr int BM = 128, BN = 128;
constexpr int ROWB = 80;                           // 64B data + 16B pad per row
constexpr int MAT = 128 * ROWB;                    // 10240 B per matrix tile
constexpr int OFF_AH = 0;
constexpr int OFF_AL = MAT;
constexpr int OFF_BH = 2 * MAT;
constexpr int OFF_BL = 3 * MAT;
constexpr int STAGE_BYTES = 4 * MAT;               // 40960 B
constexpr int DYN_SMEM = 2 * STAGE_BYTES;          // 81920 B
constexpr int NTHREADS = 128;

// ===========================================================================
// bf16x3 batched NT GEMM via mma.sync. z-mode: 0 shared, 1 z/H, 2 z%H, 3 z.
// 4 warps arranged 2(m) x 2(n); warp tile 64x64.
// MMA burst is issued in three term-passes (HH, HL, LH) so consecutive HMMAs
// never share an accumulator (acc-RAW chain removal); per-acc order is still
// HH -> HL -> LH, so numerics match previous rounds exactly.
// ===========================================================================
__global__ __launch_bounds__(NTHREADS, 2)
void gemm_bf16x3(
    const __nv_bfloat16* __restrict__ Ahi, const __nv_bfloat16* __restrict__ Alo,
    const __nv_bfloat16* __restrict__ Bhi, const __nv_bfloat16* __restrict__ Blo,
    float* __restrict__ Cf, __nv_bfloat16* __restrict__ Chi, __nv_bfloat16* __restrict__ Clo,
    int M, int N, int K,
    long long aStride, long long bStride,
    int modeA, int modeB, int H, float alpha)
{
    extern __shared__ char dynsmem[];
    const uint32_t sb = smem_u32(dynsmem);

    const int tid  = threadIdx.x;
    const int wid  = tid >> 5;
    const int lane = tid & 31;
    const int wm   = wid >> 1;            // 0..1 -> m offset 64*wm
    const int wn   = wid & 1;             // 0..1 -> n offset 64*wn

    const int z  = blockIdx.z;
    const int zA = (modeA == 0) ? 0 : (modeA == 1) ? (z / H) : (modeA == 2) ? (z % H) : z;
    const int zB = (modeB == 0) ? 0 : (modeB == 1) ? (z / H) : (modeB == 2) ? (z % H) : z;
    const __nv_bfloat16* pA[2] = { Ahi + (long long)zA * aStride, Alo + (long long)zA * aStride };
    const __nv_bfloat16* pB[2] = { Bhi + (long long)zB * bStride, Blo + (long long)zB * bStride };

    const int m0 = blockIdx.y * BM;
    const int n0 = blockIdx.x * BN;
    const int NC = K >> 5;                // chunks of 32

    auto load_stage = [&](int stage, int kc) {
        const int k0 = kc << 5;
        const uint32_t stb = sb + (uint32_t)(stage * STAGE_BYTES);
#pragma unroll
        for (int it = 0; it < 16; ++it) {
            const int idx = it * NTHREADS + tid;     // 0..2047
            const int mat = idx >> 9;                // 0..3: AH, AL, BH, BL
            const int rem = idx & 511;
            const int row = rem >> 2;                // 0..127
            const int seg = rem & 3;                 // 16B segment
            int g, lim; const __nv_bfloat16* src;
            if (mat < 2) { g = m0 + row; lim = M; src = pA[mat]; }
            else         { g = n0 + row; lim = N; src = pB[mat - 2]; }
            const int valid = (g < lim);
            const uint32_t dst = stb + (uint32_t)(mat * MAT) + (uint32_t)(row * ROWB + seg * 16);
            const char* sp = (const char*)(src + (long long)(valid ? g : 0) * K + k0 + seg * 8);
            const uint32_t sz = valid ? 16u : 0u;
            asm volatile("cp.async.cg.shared.global [%0], [%1], 16, %2;"
                         :: "r"(dst), "l"(sp), "r"(sz));
        }
        asm volatile("cp.async.commit_group;" ::: "memory");
    };

    float acc[4][8][4];
#pragma unroll
    for (int t = 0; t < 4; t++)
#pragma unroll
        for (int n = 0; n < 8; n++)
#pragma unroll
            for (int j = 0; j < 4; j++) acc[t][n][j] = 0.f;

    load_stage(0, 0);
    if (NC > 1) load_stage(1, 1);

    const uint32_t lrow = (uint32_t)(lane & 15) * ROWB;
    const uint32_t lseg = (uint32_t)(lane >> 4) * 16;

    for (int kc = 0; kc < NC; ++kc) {
        if (kc + 2 <= NC) { asm volatile("cp.async.wait_group 1;" ::: "memory"); }
        else              { asm volatile("cp.async.wait_group 0;" ::: "memory"); }
        __syncthreads();

        const int st = kc & 1;
        const uint32_t stb = sb + (uint32_t)(st * STAGE_BYTES);
        const uint32_t aHb = stb + OFF_AH, aLb = stb + OFF_AL;
        const uint32_t bHb = stb + OFF_BH, bLb = stb + OFF_BL;

#pragma unroll
        for (int kk = 0; kk < 2; ++kk) {
            const uint32_t koff = (uint32_t)kk * 32 + lseg;
            uint32_t aH[4][4], aL[4][4], bH[4][4], bL[4][4];
#pragma unroll
            for (int t = 0; t < 4; ++t) {
                const uint32_t ro = (uint32_t)(wm * 64 + t * 16) * ROWB + lrow + koff;
                ldsm_x4(aHb + ro, aH[t][0], aH[t][1], aH[t][2], aH[t][3]);
                ldsm_x4(aLb + ro, aL[t][0], aL[t][1], aL[t][2], aL[t][3]);
            }
#pragma unroll
            for (int p = 0; p < 4; ++p) {
                const uint32_t ro = (uint32_t)(wn * 64 + p * 16) * ROWB + lrow + koff;
                ldsm_x4(bHb + ro, bH[p][0], bH[p][1], bH[p][2], bH[p][3]);
                ldsm_x4(bLb + ro, bL[p][0], bL[p][1], bL[p][2], bL[p][3]);
            }
            // pass 1: Ahi * Bhi  (32 distinct accumulators)
#pragma unroll
            for (int p = 0; p < 4; ++p)
#pragma unroll
                for (int t = 0; t < 4; ++t) {
                    mma_bf16(acc[t][2*p],   aH[t], bH[p][0], bH[p][2]);
                    mma_bf16(acc[t][2*p+1], aH[t], bH[p][1], bH[p][3]);
                }
            // pass 2: Ahi * Blo
#pragma unroll
            for (int p = 0; p < 4; ++p)
#pragma unroll
                for (int t = 0; t < 4; ++t) {
                    mma_bf16(acc[t][2*p],   aH[t], bL[p][0], bL[p][2]);
                    mma_bf16(acc[t][2*p+1], aH[t], bL[p][1], bL[p][3]);
                }
            // pass 3: Alo * Bhi
#pragma unroll
            for (int p = 0; p < 4; ++p)
#pragma unroll
                for (int t = 0; t < 4; ++t) {
                    mma_bf16(acc[t][2*p],   aL[t], bH[p][0], bH[p][2]);
                    mma_bf16(acc[t][2*p+1], aL[t], bH[p][1], bH[p][3]);
                }
        }
        __syncthreads();
        if (kc + 2 < NC) load_stage(st, kc + 2);
    }

    // ------- epilogue ------------------------------------------------------
    const int grp  = lane >> 2;
    const int tid4 = lane & 3;
#pragma unroll
    for (int t = 0; t < 4; ++t) {
#pragma unroll
        for (int n = 0; n < 8; ++n) {
            const int gn = n0 + wn * 64 + n * 8 + tid4 * 2;
            if (gn >= N) continue;
#pragma unroll
            for (int half = 0; half < 2; ++half) {
                const int gm = m0 + wm * 64 + t * 16 + grp + half * 8;
                if (gm >= M) continue;
                const float v0 = alpha * acc[t][n][half * 2 + 0];
                const float v1 = alpha * acc[t][n][half * 2 + 1];
                const long long base = (long long)z * M * N + (long long)gm * N + gn;
                if (Cf) {
                    *reinterpret_cast<float2*>(Cf + base) = make_float2(v0, v1);
                } else {
                    __nv_bfloat162 hp = __floats2bfloat162_rn(v0, v1);
                    __nv_bfloat162 lp = __floats2bfloat162_rn(v0 - __bfloat162float(hp.x),
                                                              v1 - __bfloat162float(hp.y));
                    *reinterpret_cast<__nv_bfloat162*>(Chi + base) = hp;
                    *reinterpret_cast<__nv_bfloat162*>(Clo + base) = lp;
                }
            }
        }
    }
}

// ===========================================================================
// merged split: fp32 -> bf16 (hi, lo) for all input tensors in one launch.
// blockIdx.y selects the job; x-dimension grid-strides within the job.
// ===========================================================================
struct SplitJobs {
    const float* src[15];
    __nv_bfloat16* hi[15];
    __nv_bfloat16* lo[15];
    long long cnt[15];
};

__global__ __launch_bounds__(256) void split_all_kernel(SplitJobs jobs)
{
    const int j = blockIdx.y;
    const float* __restrict__ src = jobs.src[j];
    __nv_bfloat16* __restrict__ hi = jobs.hi[j];
    __nv_bfloat16* __restrict__ lo = jobs.lo[j];
    const long long n = jobs.cnt[j];
    long long i = (long long)blockIdx.x * blockDim.x + threadIdx.x;
    const long long stride = (long long)gridDim.x * blockDim.x;
    for (; i < n; i += stride) {
        const float x = src[i];
        const __nv_bfloat16 h = __float2bfloat16(x);
        hi[i] = h;
        lo[i] = __float2bfloat16(x - __bfloat162float(h));
    }
}

// ===========================================================================
// per-(b,h) biased variance over d x KV -> inv_std (mean cancels in softmax)
// ===========================================================================
__global__ __launch_bounds__(256) void stats_kernel(
    const float* __restrict__ S, float* __restrict__ invstd, int elems)
{
    const int bh = blockIdx.x;
    const float4* p = reinterpret_cast<const float4*>(S + (long long)bh * elems);
    const int n4 = elems >> 2;
    float s = 0.f, s2 = 0.f;
    for (int i = threadIdx.x; i < n4; i += 256) {
        float4 v = p[i];
        s  += v.x + v.y + v.z + v.w;
        s2 += v.x * v.x + v.y * v.y + v.z * v.z + v.w * v.w;
    }
    __shared__ float sh0[256], sh1[256];
    sh0[threadIdx.x] = s; sh1[threadIdx.x] = s2;
    __syncthreads();
    for (int off = 128; off > 0; off >>= 1) {
        if (threadIdx.x < off) {
            sh0[threadIdx.x] += sh0[threadIdx.x + off];
            sh1[threadIdx.x] += sh1[threadIdx.x + off];
        }
        __syncthreads();
    }
    if (threadIdx.x == 0) {
        const float inv = 1.f / (float)elems;
        const float m   = sh0[0] * inv;
        const float var = sh1[0] * inv - m * m;
        invstd[bh] = rsqrtf(var + 1e-5f);
    }
}

// ===========================================================================
// row softmax over KV with inv_std scaling; writes bf16 (hi, lo) pair
// ===========================================================================
__global__ __launch_bounds__(256) void softmax_kernel(
    const float* __restrict__ S, const float* __restrict__ invstd,
    __nv_bfloat16* __restrict__ Ahi, __nv_bfloat16* __restrict__ Alo,
    int d, int KV)
{
    const long long row = blockIdx.x;           // bh*d + e
    const int bh = (int)(row / d);
    const float is = invstd[bh];
    const float* p = S + row * KV;
    const long long ob = row * KV;
    const int tid = threadIdx.x;

    float vals[4];
    int cnt = 0;
    float mx = -1e30f;
    for (int i = tid; i < KV; i += 256) {
        const float v = p[i] * is;
        vals[cnt++] = v;
        mx = fmaxf(mx, v);
    }
    __shared__ float sh[256];
    sh[tid] = mx; __syncthreads();
    for (int off = 128; off > 0; off >>= 1) {
        if (tid < off) sh[tid] = fmaxf(sh[tid], sh[tid + off]);
        __syncthreads();
    }
    mx = sh[0];
    __syncthreads();

    float s = 0.f;
    for (int c = 0; c < cnt; c++) { vals[c] = __expf(vals[c] - mx); s += vals[c]; }
    sh[tid] = s; __syncthreads();
    for (int off = 128; off > 0; off >>= 1) {
        if (tid < off) sh[tid] += sh[tid + off];
        __syncthreads();
    }
    const float rs = 1.f / sh[0];
    cnt = 0;
    for (int i = tid; i < KV; i += 256) {
        const float a = vals[cnt++] * rs;
        const __nv_bfloat16 h = __float2bfloat16(a);
        Ahi[ob + i] = h;
        Alo[ob + i] = __float2bfloat16(a - __bfloat162float(h));
    }
}

// ===========================================================================
// Cm[b][n][e] = 0.25 * sum_h C[b*4+h][e][n], written as bf16 (hi, lo)
// ===========================================================================
__global__ __launch_bounds__(256) void headmean_kernel(
    const float* __restrict__ C, __nv_bfloat16* __restrict__ Cmhi,
    __nv_bfloat16* __restrict__ Cmlo, int d, int N)
{
    __shared__ float tile[32][33];
    const int b  = blockIdx.z;
    const int e0 = blockIdx.y * 32;
    const int n0 = blockIdx.x * 32;
    const int tx = threadIdx.x, ty = threadIdx.y;

    for (int r = ty; r < 32; r += 8) {
        const int e = e0 + r;
        float acc = 0.f;
#pragma unroll
        for (int h = 0; h < 4; h++)
            acc += C[(((long long)(b * 4 + h) * d + e) * N) + n0 + tx];
        tile[r][tx] = 0.25f * acc;
    }
    __syncthreads();
    for (int r = ty; r < 32; r += 8) {
        const int n = n0 + r;
        const int e = e0 + tx;
        const float v = tile[tx][r];
        const __nv_bfloat16 h = __float2bfloat16(v);
        const long long idx = ((long long)b * N + n) * d + e;
        Cmhi[idx] = h;
        Cmlo[idx] = __float2bfloat16(v - __bfloat162float(h));
    }
}

// ===========================================================================
extern "C" void kernel_launch(void* const* d_in, const int* in_sizes, int n_in,
                              void* d_out, int out_size)
{
    (void)in_sizes; (void)n_in; (void)out_size;
    const float* emb[4]  = {(const float*)d_in[0], (const float*)d_in[1],
                            (const float*)d_in[2], (const float*)d_in[3]};
    const float* emb_all = (const float*)d_in[4];
    const float* WQ[4]   = {(const float*)d_in[5], (const float*)d_in[6],
                            (const float*)d_in[7], (const float*)d_in[8]};
    const float* WK      = (const float*)d_in[9];
    const float* WV      = (const float*)d_in[10];
    const float* WO[4]   = {(const float*)d_in[11], (const float*)d_in[12],
                            (const float*)d_in[13], (const float*)d_in[14]};
    float* out = (float*)d_out;

    __nv_bfloat16 *embp[4], *embap, *wqp[4], *wkp, *wvp, *wop[4];
    __nv_bfloat16 *ktp, *vp, *qp[4], *ap, *cmp;
    float *S, *C, *invstd;
    cudaGetSymbolAddress((void**)&embp[0], g_emb1p);
    cudaGetSymbolAddress((void**)&embp[1], g_emb2p);
    cudaGetSymbolAddress((void**)&embp[2], g_emb3p);
    cudaGetSymbolAddress((void**)&embp[3], g_emb4p);
    cudaGetSymbolAddress((void**)&embap,   g_embap);
    cudaGetSymbolAddress((void**)&wqp[0],  g_wq1p);
    cudaGetSymbolAddress((void**)&wqp[1],  g_wq2p);
    cudaGetSymbolAddress((void**)&wqp[2],  g_wq3p);
    cudaGetSymbolAddress((void**)&wqp[3],  g_wq4p);
    cudaGetSymbolAddress((void**)&wkp,     g_wkp);
    cudaGetSymbolAddress((void**)&wvp,     g_wvp);
    cudaGetSymbolAddress((void**)&wop[0],  g_wo1p);
    cudaGetSymbolAddress((void**)&wop[1],  g_wo2p);
    cudaGetSymbolAddress((void**)&wop[2],  g_wo3p);
    cudaGetSymbolAddress((void**)&wop[3],  g_wo4p);
    cudaGetSymbolAddress((void**)&ktp,     g_ktp);
    cudaGetSymbolAddress((void**)&vp,      g_vp);
    cudaGetSymbolAddress((void**)&qp[0],   g_q1p);
    cudaGetSymbolAddress((void**)&qp[1],   g_q2p);
    cudaGetSymbolAddress((void**)&qp[2],   g_q3p);
    cudaGetSymbolAddress((void**)&qp[3],   g_q4p);
    cudaGetSymbolAddress((void**)&ap,      g_ap);
    cudaGetSymbolAddress((void**)&cmp,     g_cmp);
    cudaGetSymbolAddress((void**)&S,       g_S);
    cudaGetSymbolAddress((void**)&C,       g_C);
    cudaGetSymbolAddress((void**)&invstd,  g_invstd);

    cudaFuncSetAttribute(gemm_bf16x3, cudaFuncAttributeMaxDynamicSharedMemorySize, DYN_SMEM);

    const int Bsz = 8, H = 4, Nn = 1024, KV = 960;
    const int df[4] = {64, 128, 256, 512};
    const long long nEmb[4] = {N_EMB1, N_EMB2, N_EMB3, N_EMB4};
    const long long nWQ[4]  = {N_WQ1, N_WQ2, N_WQ3, N_WQ4};
    const long long nWO[4]  = {N_WO1, N_WO2, N_WO3, N_WO4};
    const long long nQ[4]   = {N_Q1, N_Q2, N_Q3, N_Q4};
    const float scale = 1.0f / sqrtf((float)KV);

    // output offsets (O1..O4 concatenated in branch order 0..3)
    long long outOff[4];
    outOff[0] = 0;
    for (int i = 1; i < 4; i++) outOff[i] = outOff[i-1] + (long long)Bsz * Nn * df[i-1];

    // ---- launch 0: merged split of all 15 inputs --------------------------
    {
        SplitJobs jobs;
        const float* srcs[15] = { emb[0], emb[1], emb[2], emb[3], emb_all,
                                  WQ[0], WQ[1], WQ[2], WQ[3], WK, WV,
                                  WO[0], WO[1], WO[2], WO[3] };
        __nv_bfloat16* dsts[15] = { embp[0], embp[1], embp[2], embp[3], embap,
                                    wqp[0], wqp[1], wqp[2], wqp[3], wkp, wvp,
                                    wop[0], wop[1], wop[2], wop[3] };
        const long long cnts[15] = { nEmb[0], nEmb[1], nEmb[2], nEmb[3], N_EMBA,
                                     nWQ[0], nWQ[1], nWQ[2], nWQ[3], N_WK, N_WV,
                                     nWO[0], nWO[1], nWO[2], nWO[3] };
        for (int i = 0; i < 15; i++) {
            jobs.src[i] = srcs[i];
            jobs.hi[i]  = dsts[i];
            jobs.lo[i]  = dsts[i] + cnts[i];
            jobs.cnt[i] = cnts[i];
        }
        split_all_kernel<<<dim3(512, 15, 1), 256>>>(jobs);
    }

    auto gemm = [&](const __nv_bfloat16* Ah, long long an,
                    const __nv_bfloat16* Bh, long long bn,
                    float* Cf, __nv_bfloat16* Ch, long long cn,
                    int M, int N, int K, long long aS, long long bS,
                    int mA, int mB, int Hh, int Z, float al) {
        dim3 g((unsigned)((N + BN - 1) / BN), (unsigned)((M + BM - 1) / BM), (unsigned)Z);
        gemm_bf16x3<<<g, NTHREADS, DYN_SMEM>>>(Ah, Ah + an, Bh, Bh + bn,
                                               Cf, Ch, Ch ? Ch + cn : nullptr,
                                               M, N, K, aS, bS, mA, mB, Hh, al);
    };

    auto launchQ = [&](int br) {
        const int d = df[br];
        gemm(wqp[br], nWQ[br], embp[br], nEmb[br], nullptr, qp[br], nQ[br],
             d, Nn, d, (long long)d*d, 1024LL*d, 2, 1, H, Bsz*H, 1.f);
    };
    auto launchS = [&](int br) {
        const int d = df[br];
        gemm(qp[br], nQ[br], ktp, N_KT, S, nullptr, 0,
             d, KV, Nn, (long long)d*1024, 960LL*1024, 3, 3, H, Bsz*H, scale);
    };
    auto finishBranch = [&](int br) {
        const int d = df[br];
        stats_kernel<<<Bsz*H, 256>>>(S, invstd, d * KV);
        softmax_kernel<<<Bsz*H*d, 256>>>(S, invstd, ap, ap + N_A, d, KV);
        gemm(ap, N_A, vp, N_VV, C, nullptr, 0,
             d, Nn, KV, (long long)d*960, 1024LL*960, 3, 3, H, Bsz*H, 1.f);
        dim3 g((unsigned)(Nn / 32), (unsigned)(d / 32), (unsigned)Bsz);
        headmean_kernel<<<g, dim3(32, 8, 1)>>>(C, cmp, cmp + N_CM, d, Nn);
        gemm(cmp, N_CM, wop[br], nWO[br], out + outOff[br], nullptr, 0,
             Nn, d, d, 1024LL*d, 0LL, 3, 0, 1, Bsz, 1.f);
    };

    // launches 1,2: KT, V (big GEMMs)
    gemm(wkp, N_WK, embap, N_EMBA, nullptr, ktp, N_KT,
         KV, Nn, KV, 960LL*960, 1024LL*960, 2, 1, H, Bsz*H, 1.f);
    gemm(embap, N_EMBA, wvp, N_WV, nullptr, vp, N_VV,
         Nn, KV, KV, 1024LL*960, 960LL*960, 1, 2, H, Bsz*H, 1.f);

    // launches 3,4,5: Q(512), S(512), Q(256) — guaranteed GEMMs around ncu -s 5
    launchQ(3);
    launchS(3);
    launchQ(2);

    finishBranch(3);
    launchS(2);
    launchQ(1);
    finishBranch(2);
    launchS(1);
    launchQ(0);
    finishBranch(1);
    launchS(0);
    finishBranch(0);
}